// round 7
// baseline (speedup 1.0000x reference)
#include <cuda_runtime.h>
#include <math.h>

// Problem constants (fixed by the dataset)
#define NN     50000
#define INF    256        // input features
#define HEADS  4
#define F0     64         // hidden per head
#define NC     40         // classes per head
#define D01    256        // HEADS*F0
#define D2     160        // HEADS*NC
#define EMAX   620000     // upper bound on edge count (~550k actual)

// -------- scratch (device globals; no allocation allowed) --------
__device__ float g_h   [(size_t)NN * D01];   // current node features (input to GEMM)
__device__ float g_feat[(size_t)NN * D01];   // post-GEMM features (per layer)
__device__ float g_out [(size_t)NN * D01];   // layer-2 output (N x 160 used)
__device__ float g_el  [NN * HEADS];
__device__ float g_er  [NN * HEADS];
__device__ float g_alpha[(size_t)EMAX * HEADS];
__device__ int   g_deg [NN];
__device__ int   g_off [NN + 1];
__device__ int   g_cur [NN];
__device__ int   g_csrc[EMAX];

// ---------------- row-normalize input: h = x / max(rowsum, 1) ----------------
__global__ void k_norm(const float* __restrict__ x) {
    int gw   = (blockIdx.x * blockDim.x + threadIdx.x) >> 5;
    int lane = threadIdx.x & 31;
    if (gw >= NN) return;
    const float* xp = x + (size_t)gw * INF;
    float s = 0.f;
    for (int f = lane; f < INF; f += 32) s += xp[f];
    for (int o = 16; o; o >>= 1) s += __shfl_xor_sync(0xffffffffu, s, o);
    float inv = 1.f / fmaxf(s, 1.f);
    float* hp = g_h + (size_t)gw * INF;
    for (int f = lane; f < INF; f += 32) hp[f] = xp[f] * inv;
}

// ---------------- CSR build (group edges by dst) ----------------
__global__ void k_zero_deg() {
    int i = blockIdx.x * blockDim.x + threadIdx.x;
    if (i < NN) g_deg[i] = 0;
}
__global__ void k_count(const int* __restrict__ dst, int E) {
    int e = blockIdx.x * blockDim.x + threadIdx.x;
    if (e < E) atomicAdd(&g_deg[dst[e]], 1);
}
__global__ void k_scan() {  // single block, 1024 threads
    __shared__ int sh[1024];
    int tid = threadIdx.x;
    const int chunk = (NN + 1023) / 1024;
    int start = tid * chunk;
    int end   = start + chunk; if (end > NN) end = NN; if (start > NN) start = NN;
    int s = 0;
    for (int i = start; i < end; i++) s += g_deg[i];
    sh[tid] = s;
    __syncthreads();
    for (int o = 1; o < 1024; o <<= 1) {
        int v = (tid >= o) ? sh[tid - o] : 0;
        __syncthreads();
        sh[tid] += v;
        __syncthreads();
    }
    int run = (tid > 0) ? sh[tid - 1] : 0;
    for (int i = start; i < end; i++) {
        g_off[i] = run; g_cur[i] = run; run += g_deg[i];
    }
    if (tid == 1023) g_off[NN] = sh[1023];
}
__global__ void k_scatter(const int* __restrict__ src, const int* __restrict__ dst, int E) {
    int e = blockIdx.x * blockDim.x + threadIdx.x;
    if (e >= E) return;
    int p = atomicAdd(&g_cur[dst[e]], 1);
    g_csrc[p] = src[e];
}

// ---------------- GEMM: g_feat = g_h @ W  (A row-major NxK, B row-major KxM) ----------------
__global__ __launch_bounds__(256) void k_gemm(const float* __restrict__ B, int k, int m) {
    __shared__ float As[8][65];
    __shared__ float Bs[8][65];
    const float* A = g_h;
    float* C = g_feat;
    int tid = threadIdx.x;
    int tx = tid & 15, ty = tid >> 4;
    int row0 = blockIdx.y * 64, col0 = blockIdx.x * 64;
    float acc[4][4];
    #pragma unroll
    for (int i = 0; i < 4; i++)
        #pragma unroll
        for (int j = 0; j < 4; j++) acc[i][j] = 0.f;

    for (int kt = 0; kt < k; kt += 8) {
        for (int i = tid; i < 64 * 8; i += 256) {
            int r = i >> 3, c = i & 7;
            int gr = row0 + r;
            As[c][r] = (gr < NN) ? A[(size_t)gr * k + kt + c] : 0.f;
        }
        for (int i = tid; i < 8 * 64; i += 256) {
            int r = i >> 6, c = i & 63;
            int gc = col0 + c;
            Bs[r][c] = (gc < m) ? B[(size_t)(kt + r) * m + gc] : 0.f;
        }
        __syncthreads();
        #pragma unroll
        for (int kk = 0; kk < 8; kk++) {
            float a0 = As[kk][ty * 4 + 0], a1 = As[kk][ty * 4 + 1];
            float a2 = As[kk][ty * 4 + 2], a3 = As[kk][ty * 4 + 3];
            float b0 = Bs[kk][tx * 4 + 0], b1 = Bs[kk][tx * 4 + 1];
            float b2 = Bs[kk][tx * 4 + 2], b3 = Bs[kk][tx * 4 + 3];
            acc[0][0] += a0 * b0; acc[0][1] += a0 * b1; acc[0][2] += a0 * b2; acc[0][3] += a0 * b3;
            acc[1][0] += a1 * b0; acc[1][1] += a1 * b1; acc[1][2] += a1 * b2; acc[1][3] += a1 * b3;
            acc[2][0] += a2 * b0; acc[2][1] += a2 * b1; acc[2][2] += a2 * b2; acc[2][3] += a2 * b3;
            acc[3][0] += a3 * b0; acc[3][1] += a3 * b1; acc[3][2] += a3 * b2; acc[3][3] += a3 * b3;
        }
        __syncthreads();
    }
    #pragma unroll
    for (int i = 0; i < 4; i++) {
        int gr = row0 + ty * 4 + i;
        if (gr < NN) {
            #pragma unroll
            for (int j = 0; j < 4; j++) {
                int gc = col0 + tx * 4 + j;
                if (gc < m) C[(size_t)gr * m + gc] = acc[i][j];
            }
        }
    }
}

// ---------------- per-node/head el, er = feat . al / ar ----------------
__global__ void k_elr(const float* __restrict__ al, const float* __restrict__ ar, int F, int D) {
    int gw   = (blockIdx.x * blockDim.x + threadIdx.x) >> 5;
    int lane = threadIdx.x & 31;
    if (gw >= NN * HEADS) return;
    int n = gw >> 2, h = gw & 3;
    const float* fp  = g_feat + (size_t)n * D + h * F;
    const float* alp = al + h * F;
    const float* arp = ar + h * F;
    float sl = 0.f, sr = 0.f;
    for (int f = lane; f < F; f += 32) {
        float v = fp[f];
        sl += v * alp[f];
        sr += v * arp[f];
    }
    for (int o = 16; o; o >>= 1) {
        sl += __shfl_xor_sync(0xffffffffu, sl, o);
        sr += __shfl_xor_sync(0xffffffffu, sr, o);
    }
    if (lane == 0) { g_el[n * 4 + h] = sl; g_er[n * 4 + h] = sr; }
}

// ---------------- edge softmax: warp per dst node ----------------
__global__ void k_attn() {
    int gw   = (blockIdx.x * blockDim.x + threadIdx.x) >> 5;
    int lane = threadIdx.x & 31;
    if (gw >= NN) return;
    int n = gw;
    float er0 = g_er[n * 4 + 0], er1 = g_er[n * 4 + 1];
    float er2 = g_er[n * 4 + 2], er3 = g_er[n * 4 + 3];
    int e0 = g_off[n], e1 = g_off[n + 1];
    float m0 = -1e30f, m1 = -1e30f, m2 = -1e30f, m3 = -1e30f;
    for (int e = e0 + lane; e < e1; e += 32) {
        int s = g_csrc[e];
        float4 el4 = *(const float4*)(g_el + (size_t)s * 4);
        float v0 = el4.x + er0; v0 = v0 > 0.f ? v0 : 0.2f * v0;
        float v1 = el4.y + er1; v1 = v1 > 0.f ? v1 : 0.2f * v1;
        float v2 = el4.z + er2; v2 = v2 > 0.f ? v2 : 0.2f * v2;
        float v3 = el4.w + er3; v3 = v3 > 0.f ? v3 : 0.2f * v3;
        float4 st; st.x = v0; st.y = v1; st.z = v2; st.w = v3;
        *(float4*)(g_alpha + (size_t)e * 4) = st;
        m0 = fmaxf(m0, v0); m1 = fmaxf(m1, v1);
        m2 = fmaxf(m2, v2); m3 = fmaxf(m3, v3);
    }
    for (int o = 16; o; o >>= 1) {
        m0 = fmaxf(m0, __shfl_xor_sync(0xffffffffu, m0, o));
        m1 = fmaxf(m1, __shfl_xor_sync(0xffffffffu, m1, o));
        m2 = fmaxf(m2, __shfl_xor_sync(0xffffffffu, m2, o));
        m3 = fmaxf(m3, __shfl_xor_sync(0xffffffffu, m3, o));
    }
    float s0 = 0.f, s1 = 0.f, s2 = 0.f, s3 = 0.f;
    for (int e = e0 + lane; e < e1; e += 32) {
        float4 v = *(float4*)(g_alpha + (size_t)e * 4);
        v.x = expf(v.x - m0); v.y = expf(v.y - m1);
        v.z = expf(v.z - m2); v.w = expf(v.w - m3);
        *(float4*)(g_alpha + (size_t)e * 4) = v;
        s0 += v.x; s1 += v.y; s2 += v.z; s3 += v.w;
    }
    for (int o = 16; o; o >>= 1) {
        s0 += __shfl_xor_sync(0xffffffffu, s0, o);
        s1 += __shfl_xor_sync(0xffffffffu, s1, o);
        s2 += __shfl_xor_sync(0xffffffffu, s2, o);
        s3 += __shfl_xor_sync(0xffffffffu, s3, o);
    }
    float r0 = 1.f / s0, r1 = 1.f / s1, r2 = 1.f / s2, r3 = 1.f / s3;
    for (int e = e0 + lane; e < e1; e += 32) {
        float4 v = *(float4*)(g_alpha + (size_t)e * 4);
        v.x *= r0; v.y *= r1; v.z *= r2; v.w *= r3;
        *(float4*)(g_alpha + (size_t)e * 4) = v;
    }
}

// ---------------- message aggregation: block per dst node ----------------
// elu != 0 : apply ELU and write to g_h (layers 0/1). elu == 0 : write g_out (layer 2).
__global__ void k_msg(const float* __restrict__ bias, int F, int D, int elu) {
    int n = blockIdx.x;
    int t = threadIdx.x;
    if (t >= D) return;
    int h = t / F;
    int e0 = g_off[n], e1 = g_off[n + 1];
    float acc = 0.f;
    for (int e = e0; e < e1; e++) {
        int s = g_csrc[e];
        acc += g_alpha[(size_t)e * 4 + h] * g_feat[(size_t)s * D + t];
    }
    acc += bias[t];
    if (elu) {
        acc = acc > 0.f ? acc : (expf(acc) - 1.f);
        g_h[(size_t)n * D + t] = acc;
    } else {
        g_out[(size_t)n * D + t] = acc;
    }
}

// ---------------- head-mean + log_softmax: warp per node ----------------
__global__ void k_final(float* __restrict__ y) {
    int gw   = (blockIdx.x * blockDim.x + threadIdx.x) >> 5;
    int lane = threadIdx.x & 31;
    if (gw >= NN) return;
    const float* op = g_out + (size_t)gw * D2;
    int c0 = lane, c1 = lane + 32;
    float v0 = -1e30f, v1 = -1e30f;
    if (c0 < NC) v0 = 0.25f * (op[c0] + op[NC + c0] + op[2 * NC + c0] + op[3 * NC + c0]);
    if (c1 < NC) v1 = 0.25f * (op[c1] + op[NC + c1] + op[2 * NC + c1] + op[3 * NC + c1]);
    float m = fmaxf(v0, v1);
    for (int o = 16; o; o >>= 1) m = fmaxf(m, __shfl_xor_sync(0xffffffffu, m, o));
    float e0 = (c0 < NC) ? expf(v0 - m) : 0.f;
    float e1 = (c1 < NC) ? expf(v1 - m) : 0.f;
    float s = e0 + e1;
    for (int o = 16; o; o >>= 1) s += __shfl_xor_sync(0xffffffffu, s, o);
    float lg = logf(s);
    if (c0 < NC) y[(size_t)gw * NC + c0] = v0 - m - lg;
    if (c1 < NC) y[(size_t)gw * NC + c1] = v1 - m - lg;
}

extern "C" void kernel_launch(void* const* d_in, const int* in_sizes, int n_in,
                              void* d_out, int out_size) {
    const float* x   = (const float*)d_in[0];
    const int*   src = (const int*)  d_in[1];
    const int*   dst = (const int*)  d_in[2];
    const float* W0  = (const float*)d_in[3];
    const float* al0 = (const float*)d_in[4];
    const float* ar0 = (const float*)d_in[5];
    const float* b0  = (const float*)d_in[6];
    const float* W1  = (const float*)d_in[7];
    const float* al1 = (const float*)d_in[8];
    const float* ar1 = (const float*)d_in[9];
    const float* b1  = (const float*)d_in[10];
    const float* W2  = (const float*)d_in[11];
    const float* al2 = (const float*)d_in[12];
    const float* ar2 = (const float*)d_in[13];
    const float* b2  = (const float*)d_in[14];
    float* y = (float*)d_out;
    int E = in_sizes[1];

    // input normalize
    k_norm<<<(NN * 32 + 255) / 256, 256>>>(x);

    // CSR by dst (graph identical for all 3 layers)
    k_zero_deg<<<(NN + 255) / 256, 256>>>();
    k_count<<<(E + 255) / 256, 256>>>(dst, E);
    k_scan<<<1, 1024>>>();
    k_scatter<<<(E + 255) / 256, 256>>>(src, dst, E);

    dim3 g01((D01 + 63) / 64, (NN + 63) / 64);
    dim3 g2 ((D2  + 63) / 64, (NN + 63) / 64);
    int elrBlocks = (NN * HEADS * 32 + 255) / 256;
    int attBlocks = (NN * 32 + 255) / 256;

    // ---- layer 0 ----
    k_gemm<<<g01, 256>>>(W0, INF, D01);
    k_elr<<<elrBlocks, 256>>>(al0, ar0, F0, D01);
    k_attn<<<attBlocks, 256>>>();
    k_msg<<<NN, D01>>>(b0, F0, D01, 1);

    // ---- layer 1 ----
    k_gemm<<<g01, 256>>>(W1, D01, D01);
    k_elr<<<elrBlocks, 256>>>(al1, ar1, F0, D01);
    k_attn<<<attBlocks, 256>>>();
    k_msg<<<NN, D01>>>(b1, F0, D01, 1);

    // ---- layer 2 ----
    k_gemm<<<g2, 256>>>(W2, D01, D2);
    k_elr<<<elrBlocks, 256>>>(al2, ar2, NC, D2);
    k_attn<<<attBlocks, 256>>>();
    k_msg<<<NN, D2>>>(b2, NC, D2, 0);

    // ---- head mean + log_softmax ----
    k_final<<<(NN * 32 + 255) / 256, 256>>>(y);
}

// round 8
// speedup vs baseline: 1.0010x; 1.0010x over previous
#include <cuda_runtime.h>
#include <math.h>

// Problem constants (fixed by the dataset)
#define NN     50000
#define INF    256        // input features
#define HEADS  4
#define F0     64         // hidden per head
#define NC     40         // classes per head
#define D01    256        // HEADS*F0
#define D2     160        // HEADS*NC
#define EMAX   620000     // upper bound on edge count (~550k actual)

// -------- scratch (device globals; no allocation allowed) --------
__device__ float g_h   [(size_t)NN * D01];   // current node features (input to GEMM)
__device__ float g_feat[(size_t)NN * D01];   // post-GEMM features (per layer)
__device__ float g_out [(size_t)NN * D01];   // layer-2 output (N x 160 used)
__device__ float g_el  [NN * HEADS];
__device__ float g_er  [NN * HEADS];
__device__ float g_alpha[(size_t)EMAX * HEADS];
__device__ int   g_deg [NN];
__device__ int   g_off [NN + 1];
__device__ int   g_cur [NN];
__device__ int   g_csrc[EMAX];

// ---------------- row-normalize input: h = x / max(rowsum, 1) ----------------
__global__ void k_norm(const float* __restrict__ x) {
    int gw   = (blockIdx.x * blockDim.x + threadIdx.x) >> 5;
    int lane = threadIdx.x & 31;
    if (gw >= NN) return;
    const float* xp = x + (size_t)gw * INF;
    float s = 0.f;
    for (int f = lane; f < INF; f += 32) s += xp[f];
    for (int o = 16; o; o >>= 1) s += __shfl_xor_sync(0xffffffffu, s, o);
    float inv = 1.f / fmaxf(s, 1.f);
    float* hp = g_h + (size_t)gw * INF;
    for (int f = lane; f < INF; f += 32) hp[f] = xp[f] * inv;
}

// ---------------- CSR build (group edges by dst) ----------------
__global__ void k_zero_deg() {
    int i = blockIdx.x * blockDim.x + threadIdx.x;
    if (i < NN) g_deg[i] = 0;
}
__global__ void k_count(const int* __restrict__ dst, int E) {
    int e = blockIdx.x * blockDim.x + threadIdx.x;
    if (e < E) atomicAdd(&g_deg[dst[e]], 1);
}
__global__ void k_scan() {  // single block, 1024 threads
    __shared__ int sh[1024];
    int tid = threadIdx.x;
    const int chunk = (NN + 1023) / 1024;
    int start = tid * chunk;
    int end   = start + chunk; if (end > NN) end = NN; if (start > NN) start = NN;
    int s = 0;
    for (int i = start; i < end; i++) s += g_deg[i];
    sh[tid] = s;
    __syncthreads();
    for (int o = 1; o < 1024; o <<= 1) {
        int v = (tid >= o) ? sh[tid - o] : 0;
        __syncthreads();
        sh[tid] += v;
        __syncthreads();
    }
    int run = (tid > 0) ? sh[tid - 1] : 0;
    for (int i = start; i < end; i++) {
        g_off[i] = run; g_cur[i] = run; run += g_deg[i];
    }
    if (tid == 1023) g_off[NN] = sh[1023];
}
__global__ void k_scatter(const int* __restrict__ src, const int* __restrict__ dst, int E) {
    int e = blockIdx.x * blockDim.x + threadIdx.x;
    if (e >= E) return;
    int p = atomicAdd(&g_cur[dst[e]], 1);
    g_csrc[p] = src[e];
}

// ---------------- GEMM: g_feat = g_h @ W  (A row-major NxK, B row-major KxM) ----------------
__global__ __launch_bounds__(256) void k_gemm(const float* __restrict__ B, int k, int m) {
    __shared__ float As[8][65];
    __shared__ float Bs[8][65];
    const float* A = g_h;
    float* C = g_feat;
    int tid = threadIdx.x;
    int tx = tid & 15, ty = tid >> 4;
    int row0 = blockIdx.y * 64, col0 = blockIdx.x * 64;
    float acc[4][4];
    #pragma unroll
    for (int i = 0; i < 4; i++)
        #pragma unroll
        for (int j = 0; j < 4; j++) acc[i][j] = 0.f;

    for (int kt = 0; kt < k; kt += 8) {
        for (int i = tid; i < 64 * 8; i += 256) {
            int r = i >> 3, c = i & 7;
            int gr = row0 + r;
            As[c][r] = (gr < NN) ? A[(size_t)gr * k + kt + c] : 0.f;
        }
        for (int i = tid; i < 8 * 64; i += 256) {
            int r = i >> 6, c = i & 63;
            int gc = col0 + c;
            Bs[r][c] = (gc < m) ? B[(size_t)(kt + r) * m + gc] : 0.f;
        }
        __syncthreads();
        #pragma unroll
        for (int kk = 0; kk < 8; kk++) {
            float a0 = As[kk][ty * 4 + 0], a1 = As[kk][ty * 4 + 1];
            float a2 = As[kk][ty * 4 + 2], a3 = As[kk][ty * 4 + 3];
            float b0 = Bs[kk][tx * 4 + 0], b1 = Bs[kk][tx * 4 + 1];
            float b2 = Bs[kk][tx * 4 + 2], b3 = Bs[kk][tx * 4 + 3];
            acc[0][0] += a0 * b0; acc[0][1] += a0 * b1; acc[0][2] += a0 * b2; acc[0][3] += a0 * b3;
            acc[1][0] += a1 * b0; acc[1][1] += a1 * b1; acc[1][2] += a1 * b2; acc[1][3] += a1 * b3;
            acc[2][0] += a2 * b0; acc[2][1] += a2 * b1; acc[2][2] += a2 * b2; acc[2][3] += a2 * b3;
            acc[3][0] += a3 * b0; acc[3][1] += a3 * b1; acc[3][2] += a3 * b2; acc[3][3] += a3 * b3;
        }
        __syncthreads();
    }
    #pragma unroll
    for (int i = 0; i < 4; i++) {
        int gr = row0 + ty * 4 + i;
        if (gr < NN) {
            #pragma unroll
            for (int j = 0; j < 4; j++) {
                int gc = col0 + tx * 4 + j;
                if (gc < m) C[(size_t)gr * m + gc] = acc[i][j];
            }
        }
    }
}

// ---------------- per-node/head el, er = feat . al / ar ----------------
__global__ void k_elr(const float* __restrict__ al, const float* __restrict__ ar, int F, int D) {
    int gw   = (blockIdx.x * blockDim.x + threadIdx.x) >> 5;
    int lane = threadIdx.x & 31;
    if (gw >= NN * HEADS) return;
    int n = gw >> 2, h = gw & 3;
    const float* fp  = g_feat + (size_t)n * D + h * F;
    const float* alp = al + h * F;
    const float* arp = ar + h * F;
    float sl = 0.f, sr = 0.f;
    for (int f = lane; f < F; f += 32) {
        float v = fp[f];
        sl += v * alp[f];
        sr += v * arp[f];
    }
    for (int o = 16; o; o >>= 1) {
        sl += __shfl_xor_sync(0xffffffffu, sl, o);
        sr += __shfl_xor_sync(0xffffffffu, sr, o);
    }
    if (lane == 0) { g_el[n * 4 + h] = sl; g_er[n * 4 + h] = sr; }
}

// ---------------- edge softmax: warp per dst node ----------------
__global__ void k_attn() {
    int gw   = (blockIdx.x * blockDim.x + threadIdx.x) >> 5;
    int lane = threadIdx.x & 31;
    if (gw >= NN) return;
    int n = gw;
    float er0 = g_er[n * 4 + 0], er1 = g_er[n * 4 + 1];
    float er2 = g_er[n * 4 + 2], er3 = g_er[n * 4 + 3];
    int e0 = g_off[n], e1 = g_off[n + 1];
    float m0 = -1e30f, m1 = -1e30f, m2 = -1e30f, m3 = -1e30f;
    for (int e = e0 + lane; e < e1; e += 32) {
        int s = g_csrc[e];
        float4 el4 = *(const float4*)(g_el + (size_t)s * 4);
        float v0 = el4.x + er0; v0 = v0 > 0.f ? v0 : 0.2f * v0;
        float v1 = el4.y + er1; v1 = v1 > 0.f ? v1 : 0.2f * v1;
        float v2 = el4.z + er2; v2 = v2 > 0.f ? v2 : 0.2f * v2;
        float v3 = el4.w + er3; v3 = v3 > 0.f ? v3 : 0.2f * v3;
        float4 st; st.x = v0; st.y = v1; st.z = v2; st.w = v3;
        *(float4*)(g_alpha + (size_t)e * 4) = st;
        m0 = fmaxf(m0, v0); m1 = fmaxf(m1, v1);
        m2 = fmaxf(m2, v2); m3 = fmaxf(m3, v3);
    }
    for (int o = 16; o; o >>= 1) {
        m0 = fmaxf(m0, __shfl_xor_sync(0xffffffffu, m0, o));
        m1 = fmaxf(m1, __shfl_xor_sync(0xffffffffu, m1, o));
        m2 = fmaxf(m2, __shfl_xor_sync(0xffffffffu, m2, o));
        m3 = fmaxf(m3, __shfl_xor_sync(0xffffffffu, m3, o));
    }
    float s0 = 0.f, s1 = 0.f, s2 = 0.f, s3 = 0.f;
    for (int e = e0 + lane; e < e1; e += 32) {
        float4 v = *(float4*)(g_alpha + (size_t)e * 4);
        v.x = expf(v.x - m0); v.y = expf(v.y - m1);
        v.z = expf(v.z - m2); v.w = expf(v.w - m3);
        *(float4*)(g_alpha + (size_t)e * 4) = v;
        s0 += v.x; s1 += v.y; s2 += v.z; s3 += v.w;
    }
    for (int o = 16; o; o >>= 1) {
        s0 += __shfl_xor_sync(0xffffffffu, s0, o);
        s1 += __shfl_xor_sync(0xffffffffu, s1, o);
        s2 += __shfl_xor_sync(0xffffffffu, s2, o);
        s3 += __shfl_xor_sync(0xffffffffu, s3, o);
    }
    float r0 = 1.f / s0, r1 = 1.f / s1, r2 = 1.f / s2, r3 = 1.f / s3;
    for (int e = e0 + lane; e < e1; e += 32) {
        float4 v = *(float4*)(g_alpha + (size_t)e * 4);
        v.x *= r0; v.y *= r1; v.z *= r2; v.w *= r3;
        *(float4*)(g_alpha + (size_t)e * 4) = v;
    }
}

// ---------------- message aggregation: block per dst node ----------------
// elu != 0 : apply ELU and write to g_h (layers 0/1). elu == 0 : write g_out (layer 2).
__global__ void k_msg(const float* __restrict__ bias, int F, int D, int elu) {
    int n = blockIdx.x;
    int t = threadIdx.x;
    if (t >= D) return;
    int h = t / F;
    int e0 = g_off[n], e1 = g_off[n + 1];
    float acc = 0.f;
    for (int e = e0; e < e1; e++) {
        int s = g_csrc[e];
        acc += g_alpha[(size_t)e * 4 + h] * g_feat[(size_t)s * D + t];
    }
    acc += bias[t];
    if (elu) {
        acc = acc > 0.f ? acc : (expf(acc) - 1.f);
        g_h[(size_t)n * D + t] = acc;
    } else {
        g_out[(size_t)n * D + t] = acc;
    }
}

// ---------------- head-mean + log_softmax: warp per node ----------------
__global__ void k_final(float* __restrict__ y) {
    int gw   = (blockIdx.x * blockDim.x + threadIdx.x) >> 5;
    int lane = threadIdx.x & 31;
    if (gw >= NN) return;
    const float* op = g_out + (size_t)gw * D2;
    int c0 = lane, c1 = lane + 32;
    float v0 = -1e30f, v1 = -1e30f;
    if (c0 < NC) v0 = 0.25f * (op[c0] + op[NC + c0] + op[2 * NC + c0] + op[3 * NC + c0]);
    if (c1 < NC) v1 = 0.25f * (op[c1] + op[NC + c1] + op[2 * NC + c1] + op[3 * NC + c1]);
    float m = fmaxf(v0, v1);
    for (int o = 16; o; o >>= 1) m = fmaxf(m, __shfl_xor_sync(0xffffffffu, m, o));
    float e0 = (c0 < NC) ? expf(v0 - m) : 0.f;
    float e1 = (c1 < NC) ? expf(v1 - m) : 0.f;
    float s = e0 + e1;
    for (int o = 16; o; o >>= 1) s += __shfl_xor_sync(0xffffffffu, s, o);
    float lg = logf(s);
    if (c0 < NC) y[(size_t)gw * NC + c0] = v0 - m - lg;
    if (c1 < NC) y[(size_t)gw * NC + c1] = v1 - m - lg;
}

extern "C" void kernel_launch(void* const* d_in, const int* in_sizes, int n_in,
                              void* d_out, int out_size) {
    const float* x   = (const float*)d_in[0];
    const int*   src = (const int*)  d_in[1];
    const int*   dst = (const int*)  d_in[2];
    const float* W0  = (const float*)d_in[3];
    const float* al0 = (const float*)d_in[4];
    const float* ar0 = (const float*)d_in[5];
    const float* b0  = (const float*)d_in[6];
    const float* W1  = (const float*)d_in[7];
    const float* al1 = (const float*)d_in[8];
    const float* ar1 = (const float*)d_in[9];
    const float* b1  = (const float*)d_in[10];
    const float* W2  = (const float*)d_in[11];
    const float* al2 = (const float*)d_in[12];
    const float* ar2 = (const float*)d_in[13];
    const float* b2  = (const float*)d_in[14];
    float* y = (float*)d_out;
    int E = in_sizes[1];

    // input normalize
    k_norm<<<(NN * 32 + 255) / 256, 256>>>(x);

    // CSR by dst (graph identical for all 3 layers)
    k_zero_deg<<<(NN + 255) / 256, 256>>>();
    k_count<<<(E + 255) / 256, 256>>>(dst, E);
    k_scan<<<1, 1024>>>();
    k_scatter<<<(E + 255) / 256, 256>>>(src, dst, E);

    dim3 g01((D01 + 63) / 64, (NN + 63) / 64);
    dim3 g2 ((D2  + 63) / 64, (NN + 63) / 64);
    int elrBlocks = (NN * HEADS * 32 + 255) / 256;
    int attBlocks = (NN * 32 + 255) / 256;

    // ---- layer 0 ----
    k_gemm<<<g01, 256>>>(W0, INF, D01);
    k_elr<<<elrBlocks, 256>>>(al0, ar0, F0, D01);
    k_attn<<<attBlocks, 256>>>();
    k_msg<<<NN, D01>>>(b0, F0, D01, 1);

    // ---- layer 1 ----
    k_gemm<<<g01, 256>>>(W1, D01, D01);
    k_elr<<<elrBlocks, 256>>>(al1, ar1, F0, D01);
    k_attn<<<attBlocks, 256>>>();
    k_msg<<<NN, D01>>>(b1, F0, D01, 1);

    // ---- layer 2 ----
    k_gemm<<<g2, 256>>>(W2, D01, D2);
    k_elr<<<elrBlocks, 256>>>(al2, ar2, NC, D2);
    k_attn<<<attBlocks, 256>>>();
    k_msg<<<NN, D2>>>(b2, NC, D2, 0);

    // ---- head mean + log_softmax ----
    k_final<<<(NN * 32 + 255) / 256, 256>>>(y);
}

// round 9
// speedup vs baseline: 1.0045x; 1.0035x over previous
#include <cuda_runtime.h>
#include <math.h>

// Problem constants (fixed by the dataset)
#define NN     50000
#define INF    256        // input features
#define HEADS  4
#define F0     64         // hidden per head
#define NC     40         // classes per head
#define D01    256        // HEADS*F0
#define D2     160        // HEADS*NC
#define EMAX   620000     // upper bound on edge count (~550k actual)

// -------- scratch (device globals; no allocation allowed) --------
__device__ float g_h   [(size_t)NN * D01];   // current node features (input to GEMM)
__device__ float g_feat[(size_t)NN * D01];   // post-GEMM features (per layer)
__device__ float g_out [(size_t)NN * D01];   // layer-2 output (N x 160 used)
__device__ float g_el  [NN * HEADS];
__device__ float g_er  [NN * HEADS];
__device__ float g_alpha[(size_t)EMAX * HEADS];
__device__ int   g_deg [NN];
__device__ int   g_off [NN + 1];
__device__ int   g_cur [NN];
__device__ int   g_csrc[EMAX];

// ---------------- row-normalize input: h = x / max(rowsum, 1) ----------------
__global__ void k_norm(const float* __restrict__ x) {
    int gw   = (blockIdx.x * blockDim.x + threadIdx.x) >> 5;
    int lane = threadIdx.x & 31;
    if (gw >= NN) return;
    const float* xp = x + (size_t)gw * INF;
    float s = 0.f;
    for (int f = lane; f < INF; f += 32) s += xp[f];
    for (int o = 16; o; o >>= 1) s += __shfl_xor_sync(0xffffffffu, s, o);
    float inv = 1.f / fmaxf(s, 1.f);
    float* hp = g_h + (size_t)gw * INF;
    for (int f = lane; f < INF; f += 32) hp[f] = xp[f] * inv;
}

// ---------------- CSR build (group edges by dst) ----------------
__global__ void k_zero_deg() {
    int i = blockIdx.x * blockDim.x + threadIdx.x;
    if (i < NN) g_deg[i] = 0;
}
__global__ void k_count(const int* __restrict__ dst, int E) {
    int e = blockIdx.x * blockDim.x + threadIdx.x;
    if (e < E) atomicAdd(&g_deg[dst[e]], 1);
}
__global__ void k_scan() {  // single block, 1024 threads
    __shared__ int sh[1024];
    int tid = threadIdx.x;
    const int chunk = (NN + 1023) / 1024;
    int start = tid * chunk;
    int end   = start + chunk; if (end > NN) end = NN; if (start > NN) start = NN;
    int s = 0;
    for (int i = start; i < end; i++) s += g_deg[i];
    sh[tid] = s;
    __syncthreads();
    for (int o = 1; o < 1024; o <<= 1) {
        int v = (tid >= o) ? sh[tid - o] : 0;
        __syncthreads();
        sh[tid] += v;
        __syncthreads();
    }
    int run = (tid > 0) ? sh[tid - 1] : 0;
    for (int i = start; i < end; i++) {
        g_off[i] = run; g_cur[i] = run; run += g_deg[i];
    }
    if (tid == 1023) g_off[NN] = sh[1023];
}
__global__ void k_scatter(const int* __restrict__ src, const int* __restrict__ dst, int E) {
    int e = blockIdx.x * blockDim.x + threadIdx.x;
    if (e >= E) return;
    int p = atomicAdd(&g_cur[dst[e]], 1);
    g_csrc[p] = src[e];
}

// ---------------- GEMM: g_feat = g_h @ W  (A row-major NxK, B row-major KxM) ----------------
__global__ __launch_bounds__(256) void k_gemm(const float* __restrict__ B, int k, int m) {
    __shared__ float As[8][65];
    __shared__ float Bs[8][65];
    const float* A = g_h;
    float* C = g_feat;
    int tid = threadIdx.x;
    int tx = tid & 15, ty = tid >> 4;
    int row0 = blockIdx.y * 64, col0 = blockIdx.x * 64;
    float acc[4][4];
    #pragma unroll
    for (int i = 0; i < 4; i++)
        #pragma unroll
        for (int j = 0; j < 4; j++) acc[i][j] = 0.f;

    for (int kt = 0; kt < k; kt += 8) {
        for (int i = tid; i < 64 * 8; i += 256) {
            int r = i >> 3, c = i & 7;
            int gr = row0 + r;
            As[c][r] = (gr < NN) ? A[(size_t)gr * k + kt + c] : 0.f;
        }
        for (int i = tid; i < 8 * 64; i += 256) {
            int r = i >> 6, c = i & 63;
            int gc = col0 + c;
            Bs[r][c] = (gc < m) ? B[(size_t)(kt + r) * m + gc] : 0.f;
        }
        __syncthreads();
        #pragma unroll
        for (int kk = 0; kk < 8; kk++) {
            float a0 = As[kk][ty * 4 + 0], a1 = As[kk][ty * 4 + 1];
            float a2 = As[kk][ty * 4 + 2], a3 = As[kk][ty * 4 + 3];
            float b0 = Bs[kk][tx * 4 + 0], b1 = Bs[kk][tx * 4 + 1];
            float b2 = Bs[kk][tx * 4 + 2], b3 = Bs[kk][tx * 4 + 3];
            acc[0][0] += a0 * b0; acc[0][1] += a0 * b1; acc[0][2] += a0 * b2; acc[0][3] += a0 * b3;
            acc[1][0] += a1 * b0; acc[1][1] += a1 * b1; acc[1][2] += a1 * b2; acc[1][3] += a1 * b3;
            acc[2][0] += a2 * b0; acc[2][1] += a2 * b1; acc[2][2] += a2 * b2; acc[2][3] += a2 * b3;
            acc[3][0] += a3 * b0; acc[3][1] += a3 * b1; acc[3][2] += a3 * b2; acc[3][3] += a3 * b3;
        }
        __syncthreads();
    }
    #pragma unroll
    for (int i = 0; i < 4; i++) {
        int gr = row0 + ty * 4 + i;
        if (gr < NN) {
            #pragma unroll
            for (int j = 0; j < 4; j++) {
                int gc = col0 + tx * 4 + j;
                if (gc < m) C[(size_t)gr * m + gc] = acc[i][j];
            }
        }
    }
}

// ---------------- per-node/head el, er = feat . al / ar ----------------
__global__ void k_elr(const float* __restrict__ al, const float* __restrict__ ar, int F, int D) {
    int gw   = (blockIdx.x * blockDim.x + threadIdx.x) >> 5;
    int lane = threadIdx.x & 31;
    if (gw >= NN * HEADS) return;
    int n = gw >> 2, h = gw & 3;
    const float* fp  = g_feat + (size_t)n * D + h * F;
    const float* alp = al + h * F;
    const float* arp = ar + h * F;
    float sl = 0.f, sr = 0.f;
    for (int f = lane; f < F; f += 32) {
        float v = fp[f];
        sl += v * alp[f];
        sr += v * arp[f];
    }
    for (int o = 16; o; o >>= 1) {
        sl += __shfl_xor_sync(0xffffffffu, sl, o);
        sr += __shfl_xor_sync(0xffffffffu, sr, o);
    }
    if (lane == 0) { g_el[n * 4 + h] = sl; g_er[n * 4 + h] = sr; }
}

// ---------------- edge softmax: warp per dst node ----------------
__global__ void k_attn() {
    int gw   = (blockIdx.x * blockDim.x + threadIdx.x) >> 5;
    int lane = threadIdx.x & 31;
    if (gw >= NN) return;
    int n = gw;
    float er0 = g_er[n * 4 + 0], er1 = g_er[n * 4 + 1];
    float er2 = g_er[n * 4 + 2], er3 = g_er[n * 4 + 3];
    int e0 = g_off[n], e1 = g_off[n + 1];
    float m0 = -1e30f, m1 = -1e30f, m2 = -1e30f, m3 = -1e30f;
    for (int e = e0 + lane; e < e1; e += 32) {
        int s = g_csrc[e];
        float4 el4 = *(const float4*)(g_el + (size_t)s * 4);
        float v0 = el4.x + er0; v0 = v0 > 0.f ? v0 : 0.2f * v0;
        float v1 = el4.y + er1; v1 = v1 > 0.f ? v1 : 0.2f * v1;
        float v2 = el4.z + er2; v2 = v2 > 0.f ? v2 : 0.2f * v2;
        float v3 = el4.w + er3; v3 = v3 > 0.f ? v3 : 0.2f * v3;
        float4 st; st.x = v0; st.y = v1; st.z = v2; st.w = v3;
        *(float4*)(g_alpha + (size_t)e * 4) = st;
        m0 = fmaxf(m0, v0); m1 = fmaxf(m1, v1);
        m2 = fmaxf(m2, v2); m3 = fmaxf(m3, v3);
    }
    for (int o = 16; o; o >>= 1) {
        m0 = fmaxf(m0, __shfl_xor_sync(0xffffffffu, m0, o));
        m1 = fmaxf(m1, __shfl_xor_sync(0xffffffffu, m1, o));
        m2 = fmaxf(m2, __shfl_xor_sync(0xffffffffu, m2, o));
        m3 = fmaxf(m3, __shfl_xor_sync(0xffffffffu, m3, o));
    }
    float s0 = 0.f, s1 = 0.f, s2 = 0.f, s3 = 0.f;
    for (int e = e0 + lane; e < e1; e += 32) {
        float4 v = *(float4*)(g_alpha + (size_t)e * 4);
        v.x = expf(v.x - m0); v.y = expf(v.y - m1);
        v.z = expf(v.z - m2); v.w = expf(v.w - m3);
        *(float4*)(g_alpha + (size_t)e * 4) = v;
        s0 += v.x; s1 += v.y; s2 += v.z; s3 += v.w;
    }
    for (int o = 16; o; o >>= 1) {
        s0 += __shfl_xor_sync(0xffffffffu, s0, o);
        s1 += __shfl_xor_sync(0xffffffffu, s1, o);
        s2 += __shfl_xor_sync(0xffffffffu, s2, o);
        s3 += __shfl_xor_sync(0xffffffffu, s3, o);
    }
    float r0 = 1.f / s0, r1 = 1.f / s1, r2 = 1.f / s2, r3 = 1.f / s3;
    for (int e = e0 + lane; e < e1; e += 32) {
        float4 v = *(float4*)(g_alpha + (size_t)e * 4);
        v.x *= r0; v.y *= r1; v.z *= r2; v.w *= r3;
        *(float4*)(g_alpha + (size_t)e * 4) = v;
    }
}

// ---------------- message aggregation: block per dst node ----------------
// elu != 0 : apply ELU and write to g_h (layers 0/1). elu == 0 : write g_out (layer 2).
__global__ void k_msg(const float* __restrict__ bias, int F, int D, int elu) {
    int n = blockIdx.x;
    int t = threadIdx.x;
    if (t >= D) return;
    int h = t / F;
    int e0 = g_off[n], e1 = g_off[n + 1];
    float acc = 0.f;
    for (int e = e0; e < e1; e++) {
        int s = g_csrc[e];
        acc += g_alpha[(size_t)e * 4 + h] * g_feat[(size_t)s * D + t];
    }
    acc += bias[t];
    if (elu) {
        acc = acc > 0.f ? acc : (expf(acc) - 1.f);
        g_h[(size_t)n * D + t] = acc;
    } else {
        g_out[(size_t)n * D + t] = acc;
    }
}

// ---------------- head-mean + log_softmax: warp per node ----------------
__global__ void k_final(float* __restrict__ y) {
    int gw   = (blockIdx.x * blockDim.x + threadIdx.x) >> 5;
    int lane = threadIdx.x & 31;
    if (gw >= NN) return;
    const float* op = g_out + (size_t)gw * D2;
    int c0 = lane, c1 = lane + 32;
    float v0 = -1e30f, v1 = -1e30f;
    if (c0 < NC) v0 = 0.25f * (op[c0] + op[NC + c0] + op[2 * NC + c0] + op[3 * NC + c0]);
    if (c1 < NC) v1 = 0.25f * (op[c1] + op[NC + c1] + op[2 * NC + c1] + op[3 * NC + c1]);
    float m = fmaxf(v0, v1);
    for (int o = 16; o; o >>= 1) m = fmaxf(m, __shfl_xor_sync(0xffffffffu, m, o));
    float e0 = (c0 < NC) ? expf(v0 - m) : 0.f;
    float e1 = (c1 < NC) ? expf(v1 - m) : 0.f;
    float s = e0 + e1;
    for (int o = 16; o; o >>= 1) s += __shfl_xor_sync(0xffffffffu, s, o);
    float lg = logf(s);
    if (c0 < NC) y[(size_t)gw * NC + c0] = v0 - m - lg;
    if (c1 < NC) y[(size_t)gw * NC + c1] = v1 - m - lg;
}

extern "C" void kernel_launch(void* const* d_in, const int* in_sizes, int n_in,
                              void* d_out, int out_size) {
    const float* x   = (const float*)d_in[0];
    const int*   src = (const int*)  d_in[1];
    const int*   dst = (const int*)  d_in[2];
    const float* W0  = (const float*)d_in[3];
    const float* al0 = (const float*)d_in[4];
    const float* ar0 = (const float*)d_in[5];
    const float* b0  = (const float*)d_in[6];
    const float* W1  = (const float*)d_in[7];
    const float* al1 = (const float*)d_in[8];
    const float* ar1 = (const float*)d_in[9];
    const float* b1  = (const float*)d_in[10];
    const float* W2  = (const float*)d_in[11];
    const float* al2 = (const float*)d_in[12];
    const float* ar2 = (const float*)d_in[13];
    const float* b2  = (const float*)d_in[14];
    float* y = (float*)d_out;
    int E = in_sizes[1];

    // input normalize
    k_norm<<<(NN * 32 + 255) / 256, 256>>>(x);

    // CSR by dst (graph identical for all 3 layers)
    k_zero_deg<<<(NN + 255) / 256, 256>>>();
    k_count<<<(E + 255) / 256, 256>>>(dst, E);
    k_scan<<<1, 1024>>>();
    k_scatter<<<(E + 255) / 256, 256>>>(src, dst, E);

    dim3 g01((D01 + 63) / 64, (NN + 63) / 64);
    dim3 g2 ((D2  + 63) / 64, (NN + 63) / 64);
    int elrBlocks = (NN * HEADS * 32 + 255) / 256;
    int attBlocks = (NN * 32 + 255) / 256;

    // ---- layer 0 ----
    k_gemm<<<g01, 256>>>(W0, INF, D01);
    k_elr<<<elrBlocks, 256>>>(al0, ar0, F0, D01);
    k_attn<<<attBlocks, 256>>>();
    k_msg<<<NN, D01>>>(b0, F0, D01, 1);

    // ---- layer 1 ----
    k_gemm<<<g01, 256>>>(W1, D01, D01);
    k_elr<<<elrBlocks, 256>>>(al1, ar1, F0, D01);
    k_attn<<<attBlocks, 256>>>();
    k_msg<<<NN, D01>>>(b1, F0, D01, 1);

    // ---- layer 2 ----
    k_gemm<<<g2, 256>>>(W2, D01, D2);
    k_elr<<<elrBlocks, 256>>>(al2, ar2, NC, D2);
    k_attn<<<attBlocks, 256>>>();
    k_msg<<<NN, D2>>>(b2, NC, D2, 0);

    // ---- head mean + log_softmax ----
    k_final<<<(NN * 32 + 255) / 256, 256>>>(y);
}